// round 1
// baseline (speedup 1.0000x reference)
#include <cuda_runtime.h>
#include <math.h>

#define BATCH 4
#define CDIM  256
#define NPIX  4096
#define CHK   32

// Scratch (static device globals — no runtime allocation)
__device__ float g_q[BATCH * NPIX * CHK];    // [b][n][32], pre-scaled + biased
__device__ float g_k[BATCH * NPIX * CHK];    // [b][n][32], biased
__device__ float g_v[BATCH * NPIX * CDIM];   // [b][n][256], biased

// ---------------------------------------------------------------------------
// Q/K projection: q[b][n][j] = scale*(sum_c wq[j][c] x[b][c][n] + bq[j])
//                 k[b][n][j] =        sum_c wk[j][c] x[b][c][n] + bk[j]
// grid (NPIX/128, BATCH), 256 threads
// ---------------------------------------------------------------------------
__global__ __launch_bounds__(256) void qk_proj(
    const float* __restrict__ x,
    const float* __restrict__ wq, const float* __restrict__ bq,
    const float* __restrict__ wk, const float* __restrict__ bk)
{
    __shared__ float wsq[32 * 33];
    __shared__ float wsk[32 * 33];
    __shared__ float xs[32 * 132];

    const int b  = blockIdx.y;
    const int n0 = blockIdx.x * 128;
    const int tid = threadIdx.x;

    const int ng = tid & 31;   // n group
    const int jg = tid >> 5;   // j group (0..7)
    const int n = ng * 4;
    const int j = jg * 4;

    float accq[4][4] = {};
    float acck[4][4] = {};

    const float* xb = x + (size_t)b * CDIM * NPIX + n0;

    for (int c0 = 0; c0 < CDIM; c0 += 32) {
        __syncthreads();
        for (int i = tid; i < 32 * 128; i += 256) {
            int cc = i >> 7, nn = i & 127;
            xs[cc * 132 + nn] = xb[(size_t)(c0 + cc) * NPIX + nn];
        }
        for (int i = tid; i < 32 * 32; i += 256) {
            int jj = i >> 5, cc = i & 31;
            wsq[jj * 33 + cc] = wq[jj * 256 + c0 + cc];
            wsk[jj * 33 + cc] = wk[jj * 256 + c0 + cc];
        }
        __syncthreads();
        #pragma unroll
        for (int cc = 0; cc < 32; cc++) {
            float4 xv = *(const float4*)&xs[cc * 132 + n];
            float xa[4] = {xv.x, xv.y, xv.z, xv.w};
            #pragma unroll
            for (int a = 0; a < 4; a++) {
                float wqv = wsq[(j + a) * 33 + cc];
                float wkv = wsk[(j + a) * 33 + cc];
                #pragma unroll
                for (int bb = 0; bb < 4; bb++) {
                    accq[a][bb] += wqv * xa[bb];
                    acck[a][bb] += wkv * xa[bb];
                }
            }
        }
    }

    const float SCALE = 0.17677669529663687f;  // 32^-0.5
    float bqr[4], bkr[4];
    #pragma unroll
    for (int a = 0; a < 4; a++) { bqr[a] = bq[j + a]; bkr[a] = bk[j + a]; }

    #pragma unroll
    for (int bb = 0; bb < 4; bb++) {
        float4 oq, ok;
        oq.x = (accq[0][bb] + bqr[0]) * SCALE;
        oq.y = (accq[1][bb] + bqr[1]) * SCALE;
        oq.z = (accq[2][bb] + bqr[2]) * SCALE;
        oq.w = (accq[3][bb] + bqr[3]) * SCALE;
        ok.x = acck[0][bb] + bkr[0];
        ok.y = acck[1][bb] + bkr[1];
        ok.z = acck[2][bb] + bkr[2];
        ok.w = acck[3][bb] + bkr[3];
        size_t off = ((size_t)b * NPIX + n0 + n + bb) * CHK + j;
        *(float4*)&g_q[off] = oq;
        *(float4*)&g_k[off] = ok;
    }
}

// ---------------------------------------------------------------------------
// V projection: v[b][n][d] = sum_c wv[d][c] x[b][c][n] + bv[d]
// grid (NPIX/128, CDIM/64, BATCH), 256 threads
// ---------------------------------------------------------------------------
__global__ __launch_bounds__(256) void v_proj(
    const float* __restrict__ x,
    const float* __restrict__ wv, const float* __restrict__ bv)
{
    __shared__ float ws[64 * 33];
    __shared__ float xs[32 * 132];

    const int b  = blockIdx.z;
    const int d0 = blockIdx.y * 64;
    const int n0 = blockIdx.x * 128;
    const int tid = threadIdx.x;

    const int dg  = tid & 15;   // d group (0..15)
    const int ngp = tid >> 4;   // n group (0..15)
    const int d = dg * 4;
    const int n = ngp * 8;

    float acc[4][8] = {};

    const float* xb = x + (size_t)b * CDIM * NPIX + n0;

    for (int c0 = 0; c0 < CDIM; c0 += 32) {
        __syncthreads();
        for (int i = tid; i < 32 * 128; i += 256) {
            int cc = i >> 7, nn = i & 127;
            xs[cc * 132 + nn] = xb[(size_t)(c0 + cc) * NPIX + nn];
        }
        for (int i = tid; i < 64 * 32; i += 256) {
            int dd = i >> 5, cc = i & 31;
            ws[dd * 33 + cc] = wv[(size_t)(d0 + dd) * 256 + c0 + cc];
        }
        __syncthreads();
        #pragma unroll
        for (int cc = 0; cc < 32; cc++) {
            float4 x0 = *(const float4*)&xs[cc * 132 + n];
            float4 x1 = *(const float4*)&xs[cc * 132 + n + 4];
            float xa[8] = {x0.x, x0.y, x0.z, x0.w, x1.x, x1.y, x1.z, x1.w};
            float wr[4];
            #pragma unroll
            for (int a = 0; a < 4; a++) wr[a] = ws[(d + a) * 33 + cc];
            #pragma unroll
            for (int a = 0; a < 4; a++)
                #pragma unroll
                for (int bb = 0; bb < 8; bb++)
                    acc[a][bb] += wr[a] * xa[bb];
        }
    }

    float bvv[4];
    #pragma unroll
    for (int a = 0; a < 4; a++) bvv[a] = bv[d0 + d + a];

    #pragma unroll
    for (int bb = 0; bb < 8; bb++) {
        float4 o;
        o.x = acc[0][bb] + bvv[0];
        o.y = acc[1][bb] + bvv[1];
        o.z = acc[2][bb] + bvv[2];
        o.w = acc[3][bb] + bvv[3];
        *(float4*)&g_v[((size_t)b * NPIX + n0 + n + bb) * CDIM + d0 + d] = o;
    }
}

// ---------------------------------------------------------------------------
// Flash attention (fp32) + gamma*out + residual, coalesced output
// grid (NPIX/64, BATCH), 256 threads, ~102KB dynamic smem
// smem layout (floats):
//   qs  [64][33]   @ 0       (2112)
//   ks  [64][33]   @ 2112    (2112)
//   ps  [64][68]   @ 4224    (4352)   P^T: [m][q]
//   vs  [64][260]  @ 8576    (16640)  [m][d]; reused as out[q][d] in epilogue
//   m_s [64] @25216, l_s [64] @25280, c_s [64] @25344   -> 25408 floats total
// ---------------------------------------------------------------------------
#define SMEM_FLOATS 25408
#define SMEM_BYTES  (SMEM_FLOATS * 4)

__global__ __launch_bounds__(256) void flash_attn(
    const float* __restrict__ x,
    const float* __restrict__ gamma,
    float* __restrict__ out)
{
    extern __shared__ float sm[];
    float* qs  = sm;
    float* ks  = sm + 2112;
    float* ps  = sm + 4224;
    float* vs  = sm + 8576;
    float* m_s = sm + 25216;
    float* l_s = sm + 25280;
    float* c_s = sm + 25344;

    const int b  = blockIdx.y;
    const int n0 = blockIdx.x * 64;
    const int tid = threadIdx.x;

    const int qg = tid >> 5;   // warp id: query group (8 queries each)
    const int dg = tid & 31;   // lane: d group (8 channels each)

    // load Q tile (pre-scaled)
    {
        const float* gq = g_q + ((size_t)b * NPIX + n0) * CHK;
        for (int i = tid; i < 64 * 32; i += 256)
            qs[(i >> 5) * 33 + (i & 31)] = gq[i];
    }
    if (tid < 64) { m_s[tid] = -1e30f; l_s[tid] = 0.f; }

    float acc[8][8] = {};

    const int mi  = (tid >> 4) * 4;   // S-compute: key micro-row
    const int qi  = (tid & 15) * 4;   // S-compute: query micro-col
    const int qi2 = tid >> 2;         // softmax: query owned
    const int sub = tid & 3;          // softmax: 4 threads per query

    for (int kt = 0; kt < NPIX / 64; kt++) {
        __syncthreads();
        // load K tile [64][32] and V tile [64][256]
        {
            const float* gk = g_k + ((size_t)b * NPIX + kt * 64) * CHK;
            for (int i = tid; i < 64 * 32; i += 256)
                ks[(i >> 5) * 33 + (i & 31)] = gk[i];
            const float4* gv = (const float4*)(g_v + ((size_t)b * NPIX + kt * 64) * CDIM);
            for (int i = tid; i < 64 * 64; i += 256) {
                int m = i >> 6, c4 = i & 63;
                *(float4*)&vs[m * 260 + c4 * 4] = gv[i];
            }
        }
        __syncthreads();

        // S^T[m][q] = K[m] . Q[q]  (4x4 micro-tile per thread)
        {
            float s[4][4] = {};
            #pragma unroll
            for (int c = 0; c < 32; c++) {
                float ka[4], qa[4];
                #pragma unroll
                for (int a = 0; a < 4; a++) ka[a] = ks[(mi + a) * 33 + c];
                #pragma unroll
                for (int bb = 0; bb < 4; bb++) qa[bb] = qs[(qi + bb) * 33 + c];
                #pragma unroll
                for (int a = 0; a < 4; a++)
                    #pragma unroll
                    for (int bb = 0; bb < 4; bb++)
                        s[a][bb] += ka[a] * qa[bb];
            }
            #pragma unroll
            for (int a = 0; a < 4; a++)
                *(float4*)&ps[(mi + a) * 68 + qi] =
                    make_float4(s[a][0], s[a][1], s[a][2], s[a][3]);
        }
        __syncthreads();

        // online softmax over this tile (4 threads per query row)
        {
            float mx = -1e30f;
            #pragma unroll
            for (int i = 0; i < 16; i++)
                mx = fmaxf(mx, ps[(sub * 16 + i) * 68 + qi2]);
            mx = fmaxf(mx, __shfl_xor_sync(0xffffffffu, mx, 1));
            mx = fmaxf(mx, __shfl_xor_sync(0xffffffffu, mx, 2));
            float mold = m_s[qi2];
            float mnew = fmaxf(mold, mx);
            float sum = 0.f;
            #pragma unroll
            for (int i = 0; i < 16; i++) {
                int o = (sub * 16 + i) * 68 + qi2;
                float p = __expf(ps[o] - mnew);
                ps[o] = p;
                sum += p;
            }
            sum += __shfl_xor_sync(0xffffffffu, sum, 1);
            sum += __shfl_xor_sync(0xffffffffu, sum, 2);
            if (sub == 0) {
                float corr = __expf(mold - mnew);
                c_s[qi2] = corr;
                l_s[qi2] = l_s[qi2] * corr + sum;
                m_s[qi2] = mnew;
            }
        }
        __syncthreads();

        // rescale + acc += P^T . V  (8x8 outer-product per thread)
        {
            float corr[8];
            #pragma unroll
            for (int i = 0; i < 8; i++) corr[i] = c_s[qg * 8 + i];
            #pragma unroll
            for (int i = 0; i < 8; i++)
                #pragma unroll
                for (int j = 0; j < 8; j++)
                    acc[i][j] *= corr[i];

            #pragma unroll 4
            for (int m = 0; m < 64; m++) {
                float4 p0 = *(const float4*)&ps[m * 68 + qg * 8];
                float4 p1 = *(const float4*)&ps[m * 68 + qg * 8 + 4];
                float4 v0 = *(const float4*)&vs[m * 260 + dg * 8];
                float4 v1 = *(const float4*)&vs[m * 260 + dg * 8 + 4];
                float pv[8] = {p0.x, p0.y, p0.z, p0.w, p1.x, p1.y, p1.z, p1.w};
                float vv[8] = {v0.x, v0.y, v0.z, v0.w, v1.x, v1.y, v1.z, v1.w};
                #pragma unroll
                for (int i = 0; i < 8; i++)
                    #pragma unroll
                    for (int j = 0; j < 8; j++)
                        acc[i][j] += pv[i] * vv[j];
            }
        }
    }

    // epilogue: normalize, gamma, transpose through smem, coalesced store + residual
    __syncthreads();
    {
        const float g = gamma[0];
        #pragma unroll
        for (int i = 0; i < 8; i++) {
            float inv = g / l_s[qg * 8 + i];
            float4 o0, o1;
            o0.x = acc[i][0] * inv; o0.y = acc[i][1] * inv;
            o0.z = acc[i][2] * inv; o0.w = acc[i][3] * inv;
            o1.x = acc[i][4] * inv; o1.y = acc[i][5] * inv;
            o1.z = acc[i][6] * inv; o1.w = acc[i][7] * inv;
            *(float4*)&vs[(qg * 8 + i) * 260 + dg * 8]     = o0;
            *(float4*)&vs[(qg * 8 + i) * 260 + dg * 8 + 4] = o1;
        }
    }
    __syncthreads();
    {
        const float* xr = x + (size_t)b * CDIM * NPIX;
        float* orow = out + (size_t)b * CDIM * NPIX;
        const int q = tid & 63;
        const int dbase = tid >> 6;   // 0..3
        #pragma unroll 4
        for (int it = 0; it < 64; it++) {
            int d = it * 4 + dbase;
            size_t go = (size_t)d * NPIX + n0 + q;
            orow[go] = vs[q * 260 + d] + xr[go];
        }
    }
}

// ---------------------------------------------------------------------------
extern "C" void kernel_launch(void* const* d_in, const int* in_sizes, int n_in,
                              void* d_out, int out_size)
{
    const float* x     = (const float*)d_in[0];
    const float* wq    = (const float*)d_in[1];
    const float* bq    = (const float*)d_in[2];
    const float* wk    = (const float*)d_in[3];
    const float* bk    = (const float*)d_in[4];
    const float* wv    = (const float*)d_in[5];
    const float* bv    = (const float*)d_in[6];
    const float* gamma = (const float*)d_in[7];
    float* out = (float*)d_out;

    qk_proj<<<dim3(NPIX / 128, BATCH), 256>>>(x, wq, bq, wk, bk);
    v_proj<<<dim3(NPIX / 128, CDIM / 64, BATCH), 256>>>(x, wv, bv);

    cudaFuncSetAttribute(flash_attn, cudaFuncAttributeMaxDynamicSharedMemorySize,
                         SMEM_BYTES);
    flash_attn<<<dim3(NPIX / 64, BATCH), 256, SMEM_BYTES>>>(x, gamma, out);
}

// round 3
// speedup vs baseline: 4.4127x; 4.4127x over previous
#include <cuda_runtime.h>
#include <cuda_bf16.h>
#include <math.h>

#define BATCH 4
#define CDIM  256
#define NPIX  4096
#define CHK   32
#define CTA_Q 64
#define KT    128

// Scratch (static device globals — no runtime allocation)
__device__ float g_q[BATCH * NPIX * CHK];              // [b][n][32], pre-scaled + biased
__device__ float g_k[BATCH * NPIX * CHK];              // [b][n][32], biased
__device__ __nv_bfloat16 g_v[BATCH * CDIM * NPIX];     // [b][d][n] bf16, biased

// ===========================================================================
// helpers
// ===========================================================================
__device__ __forceinline__ unsigned smem_u32(const void* p) {
    unsigned a;
    asm("{ .reg .u64 t; cvta.to.shared.u64 t, %1; cvt.u32.u64 %0, t; }"
        : "=r"(a) : "l"(p));
    return a;
}
__device__ __forceinline__ void sts32(unsigned a, unsigned v) {
    asm volatile("st.shared.b32 [%0], %1;" :: "r"(a), "r"(v));
}
__device__ __forceinline__ void sts128(unsigned a, uint4 v) {
    asm volatile("st.shared.v4.b32 [%0], {%1,%2,%3,%4};"
                 :: "r"(a), "r"(v.x), "r"(v.y), "r"(v.z), "r"(v.w));
}
// pack two floats -> bf16x2 (first arg = low half)
__device__ __forceinline__ unsigned bf2(float lo, float hi) {
    unsigned u;
    asm("cvt.rn.bf16x2.f32 %0, %1, %2;" : "=r"(u) : "f"(hi), "f"(lo));
    return u;
}
__device__ __forceinline__ float fexp2(float x) {
    float r; asm("ex2.approx.ftz.f32 %0, %1;" : "=f"(r) : "f"(x)); return r;
}
__device__ __forceinline__ void ldmx4(unsigned* r, unsigned addr) {
    asm volatile("ldmatrix.sync.aligned.m8n8.x4.shared.b16 {%0,%1,%2,%3}, [%4];"
                 : "=r"(r[0]), "=r"(r[1]), "=r"(r[2]), "=r"(r[3]) : "r"(addr));
}
__device__ __forceinline__ void mma16816(float* c, const unsigned* a,
                                         unsigned b0, unsigned b1) {
    asm volatile("mma.sync.aligned.m16n8k16.row.col.f32.bf16.bf16.f32 "
        "{%0,%1,%2,%3}, {%4,%5,%6,%7}, {%8,%9}, {%0,%1,%2,%3};"
        : "+f"(c[0]), "+f"(c[1]), "+f"(c[2]), "+f"(c[3])
        : "r"(a[0]), "r"(a[1]), "r"(a[2]), "r"(a[3]), "r"(b0), "r"(b1));
}

// ---------------------------------------------------------------------------
// Q/K projection (proven): fp32 g_q (pre-scaled), g_k
// ---------------------------------------------------------------------------
__global__ __launch_bounds__(256) void qk_proj(
    const float* __restrict__ x,
    const float* __restrict__ wq, const float* __restrict__ bq,
    const float* __restrict__ wk, const float* __restrict__ bk)
{
    __shared__ float wsq[32 * 33];
    __shared__ float wsk[32 * 33];
    __shared__ float xs[32 * 132];

    const int b  = blockIdx.y;
    const int n0 = blockIdx.x * 128;
    const int tid = threadIdx.x;
    const int ng = tid & 31;
    const int jg = tid >> 5;
    const int n = ng * 4;
    const int j = jg * 4;

    float accq[4][4] = {};
    float acck[4][4] = {};
    const float* xb = x + (size_t)b * CDIM * NPIX + n0;

    for (int c0 = 0; c0 < CDIM; c0 += 32) {
        __syncthreads();
        for (int i = tid; i < 32 * 128; i += 256) {
            int cc = i >> 7, nn = i & 127;
            xs[cc * 132 + nn] = xb[(size_t)(c0 + cc) * NPIX + nn];
        }
        for (int i = tid; i < 32 * 32; i += 256) {
            int jj = i >> 5, cc = i & 31;
            wsq[jj * 33 + cc] = wq[jj * 256 + c0 + cc];
            wsk[jj * 33 + cc] = wk[jj * 256 + c0 + cc];
        }
        __syncthreads();
        #pragma unroll
        for (int cc = 0; cc < 32; cc++) {
            float4 xv = *(const float4*)&xs[cc * 132 + n];
            float xa[4] = {xv.x, xv.y, xv.z, xv.w};
            #pragma unroll
            for (int a = 0; a < 4; a++) {
                float wqv = wsq[(j + a) * 33 + cc];
                float wkv = wsk[(j + a) * 33 + cc];
                #pragma unroll
                for (int bb = 0; bb < 4; bb++) {
                    accq[a][bb] += wqv * xa[bb];
                    acck[a][bb] += wkv * xa[bb];
                }
            }
        }
    }

    const float SCALE = 0.17677669529663687f;
    float bqr[4], bkr[4];
    #pragma unroll
    for (int a = 0; a < 4; a++) { bqr[a] = bq[j + a]; bkr[a] = bk[j + a]; }

    #pragma unroll
    for (int bb = 0; bb < 4; bb++) {
        float4 oq, ok;
        oq.x = (accq[0][bb] + bqr[0]) * SCALE;
        oq.y = (accq[1][bb] + bqr[1]) * SCALE;
        oq.z = (accq[2][bb] + bqr[2]) * SCALE;
        oq.w = (accq[3][bb] + bqr[3]) * SCALE;
        ok.x = acck[0][bb] + bkr[0];
        ok.y = acck[1][bb] + bkr[1];
        ok.z = acck[2][bb] + bkr[2];
        ok.w = acck[3][bb] + bkr[3];
        size_t off = ((size_t)b * NPIX + n0 + n + bb) * CHK + j;
        *(float4*)&g_q[off] = oq;
        *(float4*)&g_k[off] = ok;
    }
}

// ---------------------------------------------------------------------------
// V projection -> bf16 [b][d][n] (n contiguous)
// ---------------------------------------------------------------------------
__global__ __launch_bounds__(256) void v_proj(
    const float* __restrict__ x,
    const float* __restrict__ wv, const float* __restrict__ bv)
{
    __shared__ float ws[64 * 33];
    __shared__ float xs[32 * 132];

    const int b  = blockIdx.z;
    const int d0 = blockIdx.y * 64;
    const int n0 = blockIdx.x * 128;
    const int tid = threadIdx.x;
    const int dg  = tid & 15;
    const int ngp = tid >> 4;
    const int d = dg * 4;
    const int n = ngp * 8;

    float acc[4][8] = {};
    const float* xb = x + (size_t)b * CDIM * NPIX + n0;

    for (int c0 = 0; c0 < CDIM; c0 += 32) {
        __syncthreads();
        for (int i = tid; i < 32 * 128; i += 256) {
            int cc = i >> 7, nn = i & 127;
            xs[cc * 132 + nn] = xb[(size_t)(c0 + cc) * NPIX + nn];
        }
        for (int i = tid; i < 64 * 32; i += 256) {
            int dd = i >> 5, cc = i & 31;
            ws[dd * 33 + cc] = wv[(size_t)(d0 + dd) * 256 + c0 + cc];
        }
        __syncthreads();
        #pragma unroll
        for (int cc = 0; cc < 32; cc++) {
            float4 x0 = *(const float4*)&xs[cc * 132 + n];
            float4 x1 = *(const float4*)&xs[cc * 132 + n + 4];
            float xa[8] = {x0.x, x0.y, x0.z, x0.w, x1.x, x1.y, x1.z, x1.w};
            float wr[4];
            #pragma unroll
            for (int a = 0; a < 4; a++) wr[a] = ws[(d + a) * 33 + cc];
            #pragma unroll
            for (int a = 0; a < 4; a++)
                #pragma unroll
                for (int bb = 0; bb < 8; bb++)
                    acc[a][bb] += wr[a] * xa[bb];
        }
    }

    #pragma unroll
    for (int a = 0; a < 4; a++) {
        float bva = bv[d0 + d + a];
        uint4 o;
        o.x = bf2(acc[a][0] + bva, acc[a][1] + bva);
        o.y = bf2(acc[a][2] + bva, acc[a][3] + bva);
        o.z = bf2(acc[a][4] + bva, acc[a][5] + bva);
        o.w = bf2(acc[a][6] + bva, acc[a][7] + bva);
        size_t base = ((size_t)(b * CDIM + d0 + d + a)) * NPIX + n0 + n;
        *(uint4*)(g_v + base) = o;
    }
}

// ---------------------------------------------------------------------------
// flash attention on mma.sync bf16, no-max softmax
// CTA: 64 queries, 8 warps = 4 q-groups x 2 halves (S: key-half, PV: d-half)
// grid (64, 4), 256 threads, occ 2
//
// smem (bytes):
//   Q  [64][40 bf16]  @ 0       (80B rows,  5120)
//   K  [128][40 bf16] @ 5120    (80B rows, 10240)
//   P  [64][136 bf16] @ 15360   (272B rows, 17408)
//   V  [256][136 bf16]@ 32768   (272B rows, 69632)  (epilogue: O [64][260] f32 overlay)
//   L  [2][64] f32    @ 102400  (512)
// ---------------------------------------------------------------------------
#define SQ_OFF 0
#define SK_OFF 5120
#define SP_OFF 15360
#define SV_OFF 32768
#define SL_OFF 102400
#define DSMEM  102912
#define LOG2E  1.4426950408889634f

__global__ __launch_bounds__(256, 2) void flash_mma(
    const float* __restrict__ x,
    const float* __restrict__ gamma,
    float* __restrict__ out)
{
    extern __shared__ char smem[];
    const unsigned sb = smem_u32(smem);

    const int tid  = threadIdx.x;
    const int lane = tid & 31;
    const int warp = tid >> 5;
    const int b    = blockIdx.y;
    const int n0   = blockIdx.x * CTA_Q;
    const int qg   = warp & 3;
    const int half = warp >> 2;
    const int q0   = qg * 16;

    // ---- load Q tile (64 x 32 fp32 -> bf16) ----
    {
        int row = tid >> 2, qtr = tid & 3;
        const float* src = g_q + ((size_t)(b * NPIX + n0 + row)) * CHK + qtr * 8;
        float4 f0 = *(const float4*)src;
        float4 f1 = *(const float4*)(src + 4);
        uint4 o;
        o.x = bf2(f0.x, f0.y); o.y = bf2(f0.z, f0.w);
        o.z = bf2(f1.x, f1.y); o.w = bf2(f1.z, f1.w);
        sts128(sb + SQ_OFF + row * 80 + qtr * 16, o);
    }

    float oacc[16][4];
    #pragma unroll
    for (int i = 0; i < 16; i++)
        #pragma unroll
        for (int j = 0; j < 4; j++) oacc[i][j] = 0.f;
    float lsum0 = 0.f, lsum1 = 0.f;

    __syncthreads();

    // Q A-fragments, loaded once
    unsigned qa[2][4];
    {
        int rowa = q0 + (lane & 7) + ((lane & 8) ? 8 : 0);
        #pragma unroll
        for (int ks = 0; ks < 2; ks++)
            ldmx4(qa[ks], sb + SQ_OFF + rowa * 80 + ks * 32 + ((lane & 16) ? 16 : 0));
    }

    for (int kt = 0; kt < NPIX / KT; kt++) {
        __syncthreads();   // V/K free (prev PV done)

        // ---- K tile: 128 x 32 fp32 -> bf16 smem [key][ch] ----
        {
            int row = tid >> 1, hh = tid & 1;
            const float* src = g_k + ((size_t)(b * NPIX + kt * KT + row)) * CHK + hh * 16;
            const float4* s4 = (const float4*)src;
            float4 a0 = s4[0], a1 = s4[1], a2 = s4[2], a3 = s4[3];
            uint4 o0, o1;
            o0.x = bf2(a0.x, a0.y); o0.y = bf2(a0.z, a0.w);
            o0.z = bf2(a1.x, a1.y); o0.w = bf2(a1.z, a1.w);
            o1.x = bf2(a2.x, a2.y); o1.y = bf2(a2.z, a2.w);
            o1.z = bf2(a3.x, a3.y); o1.w = bf2(a3.z, a3.w);
            sts128(sb + SK_OFF + row * 80 + hh * 32, o0);
            sts128(sb + SK_OFF + row * 80 + hh * 32 + 16, o1);
        }
        // ---- V tile: 256 d-rows x 128 keys bf16 smem [d][k] ----
        {
            const __nv_bfloat16* vb = g_v + (size_t)b * CDIM * NPIX + kt * KT;
            #pragma unroll
            for (int it = 0; it < 8; it++) {
                int idx = it * 256 + tid;
                int d = idx >> 3, c = idx & 7;
                const uint4* s = (const uint4*)(vb + (size_t)d * NPIX + c * 16);
                uint4 v0 = s[0], v1 = s[1];
                unsigned dst = sb + SV_OFF + d * 272 + c * 32;
                sts128(dst, v0);
                sts128(dst + 16, v1);
            }
        }
        __syncthreads();

        // ---- S = Q.K^T (16q x 64k per warp), exp, P -> smem ----
        {
            const int key_base = half * 64;
            #pragma unroll
            for (int kg = 0; kg < 4; kg++) {
                const int kk0 = key_base + kg * 16;
                unsigned kb[2][4];
                #pragma unroll
                for (int ks = 0; ks < 2; ks++) {
                    int nrow = kk0 + (lane & 7) + ((lane & 16) ? 8 : 0);
                    ldmx4(kb[ks], sb + SK_OFF + nrow * 80 + ks * 32 + ((lane & 8) ? 16 : 0));
                }
                float s0[4] = {0, 0, 0, 0}, s1[4] = {0, 0, 0, 0};
                mma16816(s0, qa[0], kb[0][0], kb[0][1]);
                mma16816(s0, qa[1], kb[1][0], kb[1][1]);
                mma16816(s1, qa[0], kb[0][2], kb[0][3]);
                mma16816(s1, qa[1], kb[1][2], kb[1][3]);

                const int r = lane >> 2;
                const int cb = (lane & 3) * 2;
                #pragma unroll
                for (int nb = 0; nb < 2; nb++) {
                    float* s = nb ? s1 : s0;
                    float p0 = fexp2(s[0] * LOG2E);
                    float p1 = fexp2(s[1] * LOG2E);
                    float p2 = fexp2(s[2] * LOG2E);
                    float p3 = fexp2(s[3] * LOG2E);
                    lsum0 += p0 + p1;
                    lsum1 += p2 + p3;
                    int col = kk0 + nb * 8 + cb;
                    sts32(sb + SP_OFF + (q0 + r) * 272 + col * 2, bf2(p0, p1));
                    sts32(sb + SP_OFF + (q0 + r + 8) * 272 + col * 2, bf2(p2, p3));
                }
            }
        }
        __syncthreads();

        // ---- O += P.V^T (16q x 128d per warp over 128k) ----
        {
            const int d0 = half * 128;
            #pragma unroll
            for (int ks = 0; ks < 8; ks++) {
                unsigned pa[4];
                {
                    int rowa = q0 + (lane & 7) + ((lane & 8) ? 8 : 0);
                    ldmx4(pa, sb + SP_OFF + rowa * 272 + ks * 32 + ((lane & 16) ? 16 : 0));
                }
                #pragma unroll
                for (int dg = 0; dg < 8; dg++) {
                    unsigned vb4[4];
                    int drow = d0 + dg * 16 + (lane & 7) + ((lane & 16) ? 8 : 0);
                    ldmx4(vb4, sb + SV_OFF + drow * 272 + ks * 32 + ((lane & 8) ? 16 : 0));
                    mma16816(oacc[dg * 2 + 0], pa, vb4[0], vb4[1]);
                    mma16816(oacc[dg * 2 + 1], pa, vb4[2], vb4[3]);
                }
            }
        }
    }

    // ---- row-sum combine ----
    lsum0 += __shfl_xor_sync(0xffffffffu, lsum0, 1);
    lsum0 += __shfl_xor_sync(0xffffffffu, lsum0, 2);
    lsum1 += __shfl_xor_sync(0xffffffffu, lsum1, 1);
    lsum1 += __shfl_xor_sync(0xffffffffu, lsum1, 2);
    if ((lane & 3) == 0) {
        float* ls = (float*)(smem + SL_OFF) + half * 64;
        ls[q0 + (lane >> 2)]     = lsum0;
        ls[q0 + (lane >> 2) + 8] = lsum1;
    }
    __syncthreads();

    // ---- O frags -> smem overlay [64][260] f32 ----
    {
        float* Os = (float*)(smem + SV_OFF);
        const int d0 = half * 128;
        const int r = lane >> 2, cb = (lane & 3) * 2;
        #pragma unroll
        for (int dg = 0; dg < 8; dg++)
            #pragma unroll
            for (int nb = 0; nb < 2; nb++) {
                int dcol = d0 + dg * 16 + nb * 8 + cb;
                float* a = oacc[dg * 2 + nb];
                Os[(q0 + r) * 260 + dcol]         = a[0];
                Os[(q0 + r) * 260 + dcol + 1]     = a[1];
                Os[(q0 + r + 8) * 260 + dcol]     = a[2];
                Os[(q0 + r + 8) * 260 + dcol + 1] = a[3];
            }
    }
    __syncthreads();

    // ---- final: out[b][d][n0+q] = gamma/l * O[q][d] + x ----
    {
        const float g = gamma[0];
        const int q = tid & 63;
        const int dgr = tid >> 6;
        const float* Ls = (const float*)(smem + SL_OFF);
        const float linv = g / (Ls[q] + Ls[64 + q]);
        const float* Os = (const float*)(smem + SV_OFF);
        const float* xb = x + (size_t)b * CDIM * NPIX + n0 + q;
        float* ob = out + (size_t)b * CDIM * NPIX + n0 + q;
        #pragma unroll 8
        for (int i = 0; i < 64; i++) {
            int d = dgr * 64 + i;
            size_t go = (size_t)d * NPIX;
            ob[go] = Os[q * 260 + d] * linv + xb[go];
        }
    }
}

// ---------------------------------------------------------------------------
extern "C" void kernel_launch(void* const* d_in, const int* in_sizes, int n_in,
                              void* d_out, int out_size)
{
    const float* x     = (const float*)d_in[0];
    const float* wq    = (const float*)d_in[1];
    const float* bq    = (const float*)d_in[2];
    const float* wk    = (const float*)d_in[3];
    const float* bk    = (const float*)d_in[4];
    const float* wv    = (const float*)d_in[5];
    const float* bv    = (const float*)d_in[6];
    const float* gamma = (const float*)d_in[7];
    float* out = (float*)d_out;

    qk_proj<<<dim3(NPIX / 128, BATCH), 256>>>(x, wq, bq, wk, bk);
    v_proj<<<dim3(NPIX / 128, CDIM / 64, BATCH), 256>>>(x, wv, bv);

    cudaFuncSetAttribute(flash_mma, cudaFuncAttributeMaxDynamicSharedMemorySize, DSMEM);
    flash_mma<<<dim3(NPIX / CTA_Q, BATCH), 256, DSMEM>>>(x, gamma, out);
}

// round 4
// speedup vs baseline: 7.6259x; 1.7281x over previous
#include <cuda_runtime.h>
#include <cuda_bf16.h>
#include <math.h>

#define BATCH 4
#define CDIM  256
#define NPIX  4096
#define CHK   32
#define CTA_Q 64
#define KT    128
#define SCALE 0.17677669529663687f
#define LOG2E 1.4426950408889634f

// Scratch (static device globals — no runtime allocation)
__device__ float g_q[BATCH * NPIX * CHK];              // [b][n][32], pre-scaled + biased
__device__ float g_k[BATCH * NPIX * CHK];              // [b][n][32], biased
__device__ __nv_bfloat16 g_v[BATCH * CDIM * NPIX];     // [b][d][n] bf16, biased

// ===========================================================================
// helpers
// ===========================================================================
__device__ __forceinline__ unsigned smem_u32(const void* p) {
    unsigned a;
    asm("{ .reg .u64 t; cvta.to.shared.u64 t, %1; cvt.u32.u64 %0, t; }"
        : "=r"(a) : "l"(p));
    return a;
}
__device__ __forceinline__ void sts32(unsigned a, unsigned v) {
    asm volatile("st.shared.b32 [%0], %1;" :: "r"(a), "r"(v));
}
__device__ __forceinline__ void sts128(unsigned a, uint4 v) {
    asm volatile("st.shared.v4.b32 [%0], {%1,%2,%3,%4};"
                 :: "r"(a), "r"(v.x), "r"(v.y), "r"(v.z), "r"(v.w));
}
// pack two floats -> bf16x2 (first arg = low half)
__device__ __forceinline__ unsigned bf2(float lo, float hi) {
    unsigned u;
    asm("cvt.rn.bf16x2.f32 %0, %1, %2;" : "=r"(u) : "f"(hi), "f"(lo));
    return u;
}
__device__ __forceinline__ float fexp2(float x) {
    float r; asm("ex2.approx.ftz.f32 %0, %1;" : "=f"(r) : "f"(x)); return r;
}
__device__ __forceinline__ void ldmx4(unsigned* r, unsigned addr) {
    asm volatile("ldmatrix.sync.aligned.m8n8.x4.shared.b16 {%0,%1,%2,%3}, [%4];"
                 : "=r"(r[0]), "=r"(r[1]), "=r"(r[2]), "=r"(r[3]) : "r"(addr));
}
__device__ __forceinline__ void mma16816(float* c, const unsigned* a,
                                         unsigned b0, unsigned b1) {
    asm volatile("mma.sync.aligned.m16n8k16.row.col.f32.bf16.bf16.f32 "
        "{%0,%1,%2,%3}, {%4,%5,%6,%7}, {%8,%9}, {%0,%1,%2,%3};"
        : "+f"(c[0]), "+f"(c[1]), "+f"(c[2]), "+f"(c[3])
        : "r"(a[0]), "r"(a[1]), "r"(a[2]), "r"(a[3]), "r"(b0), "r"(b1));
}
#define CP16(dst, src) \
    asm volatile("cp.async.cg.shared.global [%0], [%1], 16;" \
                 :: "r"(dst), "l"(src))
#define CP_COMMIT() asm volatile("cp.async.commit_group;" ::: "memory")
#define CP_WAIT0()  asm volatile("cp.async.wait_group 0;" ::: "memory")

// ---------------------------------------------------------------------------
// Fused QKV projection on mma.sync bf16.
// out rows o: [0,32)=q, [32,64)=k, [64,320)=v.  GEMM [320][4096] = W[320][256] X[256][4096]
// grid (32, 4), 512 threads.  Warp: 80 o (5 m16) x 32 n (4 n8).
// smem: XT [128 n][528B rows] (256 c bf16 + 16B pad)  @ 0      (67584)
//       WS [320 o][144B rows] (64 c bf16 + 16B pad)   @ 67584  (46080)
// ---------------------------------------------------------------------------
#define PROJ_SMEM (67584 + 46080)

__global__ __launch_bounds__(512, 1) void qkv_proj(
    const float* __restrict__ x,
    const float* __restrict__ wq, const float* __restrict__ bq,
    const float* __restrict__ wk, const float* __restrict__ bk,
    const float* __restrict__ wv, const float* __restrict__ bv)
{
    extern __shared__ char smem[];
    const unsigned sb = smem_u32(smem);
    const unsigned XT = sb;
    const unsigned WS = sb + 67584;

    const int tid  = threadIdx.x;
    const int lane = tid & 31;
    const int warp = tid >> 5;
    const int b    = blockIdx.y;
    const int n0   = blockIdx.x * 128;
    const int obase = (warp & 3) * 80;
    const int nbase = (warp >> 2) * 32;

    // ---- X^T tile: gmem [c][n] fp32 -> smem [n][c] bf16 (c-pairs packed) ----
    {
        const float* xb = x + (size_t)b * CDIM * NPIX + n0;
        #pragma unroll
        for (int it = 0; it < 32; it++) {
            int idx = it * 512 + tid;
            int cp = idx >> 7;             // c-pair 0..127
            int n  = idx & 127;
            float v0 = xb[(size_t)(2 * cp) * NPIX + n];
            float v1 = xb[(size_t)(2 * cp + 1) * NPIX + n];
            sts32(XT + n * 528 + cp * 4, bf2(v0, v1));
        }
    }

    float acc[5][4][4];
    #pragma unroll
    for (int t = 0; t < 5; t++)
        #pragma unroll
        for (int f = 0; f < 4; f++)
            #pragma unroll
            for (int j = 0; j < 4; j++) acc[t][f][j] = 0.f;

    for (int ch = 0; ch < 4; ch++) {
        __syncthreads();
        // ---- W chunk [320][64] fp32 -> bf16 smem ----
        #pragma unroll
        for (int it = 0; it < 10; it++) {
            int idx = it * 512 + tid;      // 0..5119
            int row = idx >> 4;
            int f4  = idx & 15;
            const float* src;
            if (row < 32)      src = wq + row * 256;
            else if (row < 64) src = wk + (row - 32) * 256;
            else               src = wv + (size_t)(row - 64) * 256;
            float4 w4 = *(const float4*)(src + ch * 64 + f4 * 4);
            sts32(WS + row * 144 + f4 * 8,     bf2(w4.x, w4.y));
            sts32(WS + row * 144 + f4 * 8 + 4, bf2(w4.z, w4.w));
        }
        __syncthreads();

        #pragma unroll
        for (int ks = 0; ks < 4; ks++) {
            unsigned bfr[2][4];
            #pragma unroll
            for (int j = 0; j < 2; j++) {
                int nrow = nbase + j * 16 + (lane & 7) + ((lane & 16) ? 8 : 0);
                ldmx4(bfr[j], XT + nrow * 528 + ch * 128 + ks * 32 +
                              ((lane & 8) ? 16 : 0));
            }
            #pragma unroll
            for (int t = 0; t < 5; t++) {
                unsigned afr[4];
                int rowa = obase + t * 16 + (lane & 7) + ((lane & 8) ? 8 : 0);
                ldmx4(afr, WS + rowa * 144 + ks * 32 + ((lane & 16) ? 16 : 0));
                mma16816(acc[t][0], afr, bfr[0][0], bfr[0][1]);
                mma16816(acc[t][1], afr, bfr[0][2], bfr[0][3]);
                mma16816(acc[t][2], afr, bfr[1][0], bfr[1][1]);
                mma16816(acc[t][3], afr, bfr[1][2], bfr[1][3]);
            }
        }
    }

    // ---- epilogue: bias (+scale for q) and store ----
    {
        const int r = lane >> 2, cb = (lane & 3) * 2;
        #pragma unroll
        for (int t = 0; t < 5; t++) {
            const int o16 = obase + t * 16;
            #pragma unroll
            for (int h = 0; h < 2; h++) {
                const int o = o16 + h * 8 + r;
                if (o < 32) {
                    float bias = bq[o];
                    #pragma unroll
                    for (int f = 0; f < 4; f++) {
                        int n = nbase + f * 8 + cb;
                        size_t base = ((size_t)(b * NPIX) + n0 + n) * CHK + o;
                        g_q[base]       = (acc[t][f][h * 2]     + bias) * SCALE;
                        g_q[base + CHK] = (acc[t][f][h * 2 + 1] + bias) * SCALE;
                    }
                } else if (o < 64) {
                    float bias = bk[o - 32];
                    #pragma unroll
                    for (int f = 0; f < 4; f++) {
                        int n = nbase + f * 8 + cb;
                        size_t base = ((size_t)(b * NPIX) + n0 + n) * CHK + (o - 32);
                        g_k[base]       = acc[t][f][h * 2]     + bias;
                        g_k[base + CHK] = acc[t][f][h * 2 + 1] + bias;
                    }
                } else {
                    float bias = bv[o - 64];
                    #pragma unroll
                    for (int f = 0; f < 4; f++) {
                        int n = nbase + f * 8 + cb;
                        unsigned u = bf2(acc[t][f][h * 2] + bias,
                                         acc[t][f][h * 2 + 1] + bias);
                        *(unsigned*)(g_v + ((size_t)(b * CDIM + o - 64)) * NPIX
                                     + n0 + n) = u;
                    }
                }
            }
        }
    }
}

// ---------------------------------------------------------------------------
// flash attention on mma.sync bf16, no-max softmax (proven round-3 kernel,
// V load switched to cp.async)
// ---------------------------------------------------------------------------
#define SQ_OFF 0
#define SK_OFF 5120
#define SP_OFF 15360
#define SV_OFF 32768
#define SL_OFF 102400
#define DSMEM  102912

__global__ __launch_bounds__(256, 2) void flash_mma(
    const float* __restrict__ x,
    const float* __restrict__ gamma,
    float* __restrict__ out)
{
    extern __shared__ char smem[];
    const unsigned sb = smem_u32(smem);

    const int tid  = threadIdx.x;
    const int lane = tid & 31;
    const int warp = tid >> 5;
    const int b    = blockIdx.y;
    const int n0   = blockIdx.x * CTA_Q;
    const int qg   = warp & 3;
    const int half = warp >> 2;
    const int q0   = qg * 16;

    // ---- load Q tile (64 x 32 fp32 -> bf16) ----
    {
        int row = tid >> 2, qtr = tid & 3;
        const float* src = g_q + ((size_t)(b * NPIX + n0 + row)) * CHK + qtr * 8;
        float4 f0 = *(const float4*)src;
        float4 f1 = *(const float4*)(src + 4);
        uint4 o;
        o.x = bf2(f0.x, f0.y); o.y = bf2(f0.z, f0.w);
        o.z = bf2(f1.x, f1.y); o.w = bf2(f1.z, f1.w);
        sts128(sb + SQ_OFF + row * 80 + qtr * 16, o);
    }

    float oacc[16][4];
    #pragma unroll
    for (int i = 0; i < 16; i++)
        #pragma unroll
        for (int j = 0; j < 4; j++) oacc[i][j] = 0.f;
    float lsum0 = 0.f, lsum1 = 0.f;

    __syncthreads();

    unsigned qa[2][4];
    {
        int rowa = q0 + (lane & 7) + ((lane & 8) ? 8 : 0);
        #pragma unroll
        for (int ks = 0; ks < 2; ks++)
            ldmx4(qa[ks], sb + SQ_OFF + rowa * 80 + ks * 32 + ((lane & 16) ? 16 : 0));
    }

    for (int kt = 0; kt < NPIX / KT; kt++) {
        __syncthreads();

        // ---- V tile via cp.async: 256 d-rows x 128 keys bf16 ----
        {
            const __nv_bfloat16* vb = g_v + (size_t)b * CDIM * NPIX + kt * KT;
            #pragma unroll
            for (int it = 0; it < 16; it++) {
                int idx = it * 256 + tid;
                int d = idx >> 4, c = idx & 15;
                CP16(sb + SV_OFF + d * 272 + c * 16, vb + (size_t)d * NPIX + c * 8);
            }
            CP_COMMIT();
        }
        // ---- K tile: 128 x 32 fp32 -> bf16 smem [key][ch] ----
        {
            int row = tid >> 1, hh = tid & 1;
            const float* src = g_k + ((size_t)(b * NPIX + kt * KT + row)) * CHK + hh * 16;
            const float4* s4 = (const float4*)src;
            float4 a0 = s4[0], a1 = s4[1], a2 = s4[2], a3 = s4[3];
            uint4 o0, o1;
            o0.x = bf2(a0.x, a0.y); o0.y = bf2(a0.z, a0.w);
            o0.z = bf2(a1.x, a1.y); o0.w = bf2(a1.z, a1.w);
            o1.x = bf2(a2.x, a2.y); o1.y = bf2(a2.z, a2.w);
            o1.z = bf2(a3.x, a3.y); o1.w = bf2(a3.z, a3.w);
            sts128(sb + SK_OFF + row * 80 + hh * 32, o0);
            sts128(sb + SK_OFF + row * 80 + hh * 32 + 16, o1);
        }
        CP_WAIT0();
        __syncthreads();

        // ---- S = Q.K^T (16q x 64k per warp), exp, P -> smem ----
        {
            const int key_base = half * 64;
            #pragma unroll
            for (int kg = 0; kg < 4; kg++) {
                const int kk0 = key_base + kg * 16;
                unsigned kb[2][4];
                #pragma unroll
                for (int ks = 0; ks < 2; ks++) {
                    int nrow = kk0 + (lane & 7) + ((lane & 16) ? 8 : 0);
                    ldmx4(kb[ks], sb + SK_OFF + nrow * 80 + ks * 32 + ((lane & 8) ? 16 : 0));
                }
                float s0[4] = {0, 0, 0, 0}, s1[4] = {0, 0, 0, 0};
                mma16816(s0, qa[0], kb[0][0], kb[0][1]);
                mma16816(s0, qa[1], kb[1][0], kb[1][1]);
                mma16816(s1, qa[0], kb[0][2], kb[0][3]);
                mma16816(s1, qa[1], kb[1][2], kb[1][3]);

                const int r = lane >> 2;
                const int cb = (lane & 3) * 2;
                #pragma unroll
                for (int nb = 0; nb < 2; nb++) {
                    float* s = nb ? s1 : s0;
                    float p0 = fexp2(s[0] * LOG2E);
                    float p1 = fexp2(s[1] * LOG2E);
                    float p2 = fexp2(s[2] * LOG2E);
                    float p3 = fexp2(s[3] * LOG2E);
                    lsum0 += p0 + p1;
                    lsum1 += p2 + p3;
                    int col = kk0 + nb * 8 + cb;
                    sts32(sb + SP_OFF + (q0 + r) * 272 + col * 2, bf2(p0, p1));
                    sts32(sb + SP_OFF + (q0 + r + 8) * 272 + col * 2, bf2(p2, p3));
                }
            }
        }
        __syncthreads();

        // ---- O += P.V^T (16q x 128d per warp over 128k) ----
        {
            const int d0 = half * 128;
            #pragma unroll
            for (int ks = 0; ks < 8; ks++) {
                unsigned pa[4];
                {
                    int rowa = q0 + (lane & 7) + ((lane & 8) ? 8 : 0);
                    ldmx4(pa, sb + SP_OFF + rowa * 272 + ks * 32 + ((lane & 16) ? 16 : 0));
                }
                #pragma unroll
                for (int dg = 0; dg < 8; dg++) {
                    unsigned vb4[4];
                    int drow = d0 + dg * 16 + (lane & 7) + ((lane & 16) ? 8 : 0);
                    ldmx4(vb4, sb + SV_OFF + drow * 272 + ks * 32 + ((lane & 8) ? 16 : 0));
                    mma16816(oacc[dg * 2 + 0], pa, vb4[0], vb4[1]);
                    mma16816(oacc[dg * 2 + 1], pa, vb4[2], vb4[3]);
                }
            }
        }
    }

    // ---- row-sum combine ----
    lsum0 += __shfl_xor_sync(0xffffffffu, lsum0, 1);
    lsum0 += __shfl_xor_sync(0xffffffffu, lsum0, 2);
    lsum1 += __shfl_xor_sync(0xffffffffu, lsum1, 1);
    lsum1 += __shfl_xor_sync(0xffffffffu, lsum1, 2);
    if ((lane & 3) == 0) {
        float* ls = (float*)(smem + SL_OFF) + half * 64;
        ls[q0 + (lane >> 2)]     = lsum0;
        ls[q0 + (lane >> 2) + 8] = lsum1;
    }
    __syncthreads();

    // ---- O frags -> smem overlay [64][260] f32 ----
    {
        float* Os = (float*)(smem + SV_OFF);
        const int d0 = half * 128;
        const int r = lane >> 2, cb = (lane & 3) * 2;
        #pragma unroll
        for (int dg = 0; dg < 8; dg++)
            #pragma unroll
            for (int nb = 0; nb < 2; nb++) {
                int dcol = d0 + dg * 16 + nb * 8 + cb;
                float* a = oacc[dg * 2 + nb];
                Os[(q0 + r) * 260 + dcol]         = a[0];
                Os[(q0 + r) * 260 + dcol + 1]     = a[1];
                Os[(q0 + r + 8) * 260 + dcol]     = a[2];
                Os[(q0 + r + 8) * 260 + dcol + 1] = a[3];
            }
    }
    __syncthreads();

    // ---- final: out[b][d][n0+q] = gamma/l * O[q][d] + x ----
    {
        const float g = gamma[0];
        const int q = tid & 63;
        const int dgr = tid >> 6;
        const float* Ls = (const float*)(smem + SL_OFF);
        const float linv = g / (Ls[q] + Ls[64 + q]);
        const float* Os = (const float*)(smem + SV_OFF);
        const float* xb = x + (size_t)b * CDIM * NPIX + n0 + q;
        float* ob = out + (size_t)b * CDIM * NPIX + n0 + q;
        #pragma unroll 8
        for (int i = 0; i < 64; i++) {
            int d = dgr * 64 + i;
            size_t go = (size_t)d * NPIX;
            ob[go] = Os[q * 260 + d] * linv + xb[go];
        }
    }
}

// ---------------------------------------------------------------------------
extern "C" void kernel_launch(void* const* d_in, const int* in_sizes, int n_in,
                              void* d_out, int out_size)
{
    const float* x     = (const float*)d_in[0];
    const float* wq    = (const float*)d_in[1];
    const float* bq    = (const float*)d_in[2];
    const float* wk    = (const float*)d_in[3];
    const float* bk    = (const float*)d_in[4];
    const float* wv    = (const float*)d_in[5];
    const float* bv    = (const float*)d_in[6];
    const float* gamma = (const float*)d_in[7];
    float* out = (float*)d_out;

    cudaFuncSetAttribute(qkv_proj, cudaFuncAttributeMaxDynamicSharedMemorySize,
                         PROJ_SMEM);
    qkv_proj<<<dim3(NPIX / 128, BATCH), 512, PROJ_SMEM>>>(x, wq, bq, wk, bk, wv, bv);

    cudaFuncSetAttribute(flash_mma, cudaFuncAttributeMaxDynamicSharedMemorySize,
                         DSMEM);
    flash_mma<<<dim3(NPIX / CTA_Q, BATCH), 256, DSMEM>>>(x, gamma, out);
}

// round 5
// speedup vs baseline: 8.4602x; 1.1094x over previous
#include <cuda_runtime.h>
#include <cuda_bf16.h>
#include <math.h>

#define BATCH 4
#define CDIM  256
#define NPIX  4096
#define CHK   32
#define CTA_Q 64
#define KT    128
#define SCALE 0.17677669529663687f
#define LOG2E 1.4426950408889634f

// Scratch (static device globals — no runtime allocation)
// Q/K: bf16, [b][n][40] rows of 80B (32 ch + 8 pad), ldmatrix-ready
__device__ __nv_bfloat16 g_q[BATCH * NPIX * 40];
__device__ __nv_bfloat16 g_k[BATCH * NPIX * 40];
__device__ __nv_bfloat16 g_v[BATCH * CDIM * NPIX];     // [b][d][n]

// ===========================================================================
// helpers
// ===========================================================================
__device__ __forceinline__ unsigned smem_u32(const void* p) {
    unsigned a;
    asm("{ .reg .u64 t; cvta.to.shared.u64 t, %1; cvt.u32.u64 %0, t; }"
        : "=r"(a) : "l"(p));
    return a;
}
__device__ __forceinline__ void sts16(unsigned a, unsigned short v) {
    asm volatile("st.shared.u16 [%0], %1;" :: "r"(a), "h"(v));
}
__device__ __forceinline__ void sts32(unsigned a, unsigned v) {
    asm volatile("st.shared.b32 [%0], %1;" :: "r"(a), "r"(v));
}
__device__ __forceinline__ unsigned bf2(float lo, float hi) {
    unsigned u;
    asm("cvt.rn.bf16x2.f32 %0, %1, %2;" : "=r"(u) : "f"(hi), "f"(lo));
    return u;
}
__device__ __forceinline__ float fexp2(float x) {
    float r; asm("ex2.approx.ftz.f32 %0, %1;" : "=f"(r) : "f"(x)); return r;
}
__device__ __forceinline__ void ldmx4(unsigned* r, unsigned addr) {
    asm volatile("ldmatrix.sync.aligned.m8n8.x4.shared.b16 {%0,%1,%2,%3}, [%4];"
                 : "=r"(r[0]), "=r"(r[1]), "=r"(r[2]), "=r"(r[3]) : "r"(addr));
}
__device__ __forceinline__ void mma16816(float* c, const unsigned* a,
                                         unsigned b0, unsigned b1) {
    asm volatile("mma.sync.aligned.m16n8k16.row.col.f32.bf16.bf16.f32 "
        "{%0,%1,%2,%3}, {%4,%5,%6,%7}, {%8,%9}, {%0,%1,%2,%3};"
        : "+f"(c[0]), "+f"(c[1]), "+f"(c[2]), "+f"(c[3])
        : "r"(a[0]), "r"(a[1]), "r"(a[2]), "r"(a[3]), "r"(b0), "r"(b1));
}
#define CP16(dst, src) \
    asm volatile("cp.async.cg.shared.global [%0], [%1], 16;" \
                 :: "r"(dst), "l"(src))
#define CP_COMMIT() asm volatile("cp.async.commit_group;" ::: "memory")
#define CP_WAIT0()  asm volatile("cp.async.wait_group 0;" ::: "memory")
#define CP_WAIT1()  asm volatile("cp.async.wait_group 1;" ::: "memory")

// ---------------------------------------------------------------------------
// Fused QKV projection on mma.sync bf16 (proven round-4 kernel; epilogue now
// emits Q/K as bf16 [n][40]-row tiles via an smem transpose).
// ---------------------------------------------------------------------------
#define PROJ_SMEM (67584 + 46080)

__global__ __launch_bounds__(512, 1) void qkv_proj(
    const float* __restrict__ x,
    const float* __restrict__ wq, const float* __restrict__ bq,
    const float* __restrict__ wk, const float* __restrict__ bk,
    const float* __restrict__ wv, const float* __restrict__ bv)
{
    extern __shared__ char smem[];
    const unsigned sb = smem_u32(smem);
    const unsigned XT = sb;
    const unsigned WS = sb + 67584;

    const int tid  = threadIdx.x;
    const int lane = tid & 31;
    const int warp = tid >> 5;
    const int b    = blockIdx.y;
    const int n0   = blockIdx.x * 128;
    const int obase = (warp & 3) * 80;
    const int nbase = (warp >> 2) * 32;

    // ---- X^T tile: gmem [c][n] fp32 -> smem [n][c] bf16 (c-pairs packed) ----
    {
        const float* xb = x + (size_t)b * CDIM * NPIX + n0;
        #pragma unroll
        for (int it = 0; it < 32; it++) {
            int idx = it * 512 + tid;
            int cp = idx >> 7;
            int n  = idx & 127;
            float v0 = xb[(size_t)(2 * cp) * NPIX + n];
            float v1 = xb[(size_t)(2 * cp + 1) * NPIX + n];
            sts32(XT + n * 528 + cp * 4, bf2(v0, v1));
        }
    }

    float acc[5][4][4];
    #pragma unroll
    for (int t = 0; t < 5; t++)
        #pragma unroll
        for (int f = 0; f < 4; f++)
            #pragma unroll
            for (int j = 0; j < 4; j++) acc[t][f][j] = 0.f;

    for (int ch = 0; ch < 4; ch++) {
        __syncthreads();
        #pragma unroll
        for (int it = 0; it < 10; it++) {
            int idx = it * 512 + tid;
            int row = idx >> 4;
            int f4  = idx & 15;
            const float* src;
            if (row < 32)      src = wq + row * 256;
            else if (row < 64) src = wk + (row - 32) * 256;
            else               src = wv + (size_t)(row - 64) * 256;
            float4 w4 = *(const float4*)(src + ch * 64 + f4 * 4);
            sts32(WS + row * 144 + f4 * 8,     bf2(w4.x, w4.y));
            sts32(WS + row * 144 + f4 * 8 + 4, bf2(w4.z, w4.w));
        }
        __syncthreads();

        #pragma unroll
        for (int ks = 0; ks < 4; ks++) {
            unsigned bfr[2][4];
            #pragma unroll
            for (int j = 0; j < 2; j++) {
                int nrow = nbase + j * 16 + (lane & 7) + ((lane & 16) ? 8 : 0);
                ldmx4(bfr[j], XT + nrow * 528 + ch * 128 + ks * 32 +
                              ((lane & 8) ? 16 : 0));
            }
            #pragma unroll
            for (int t = 0; t < 5; t++) {
                unsigned afr[4];
                int rowa = obase + t * 16 + (lane & 7) + ((lane & 8) ? 8 : 0);
                ldmx4(afr, WS + rowa * 144 + ks * 32 + ((lane & 16) ? 16 : 0));
                mma16816(acc[t][0], afr, bfr[0][0], bfr[0][1]);
                mma16816(acc[t][1], afr, bfr[0][2], bfr[0][3]);
                mma16816(acc[t][2], afr, bfr[1][0], bfr[1][1]);
                mma16816(acc[t][3], afr, bfr[1][2], bfr[1][3]);
            }
        }
    }

    __syncthreads();   // XT/WS reads done; reuse XT region for q/k transpose
    // staging: Qstage [128 n][80B] @ XT, Kstage [128 n][80B] @ XT+10240
    {
        const int r = lane >> 2, cb = (lane & 3) * 2;
        #pragma unroll
        for (int t = 0; t < 5; t++) {
            const int o16 = obase + t * 16;
            #pragma unroll
            for (int h = 0; h < 2; h++) {
                const int o = o16 + h * 8 + r;
                if (o < 32) {
                    float bias = bq[o];
                    #pragma unroll
                    for (int f = 0; f < 4; f++) {
                        int n = nbase + f * 8 + cb;
                        unsigned u = bf2((acc[t][f][h * 2]     + bias) * SCALE,
                                         (acc[t][f][h * 2 + 1] + bias) * SCALE);
                        sts16(XT + n * 80 + o * 2,       (unsigned short)(u & 0xffff));
                        sts16(XT + (n + 1) * 80 + o * 2, (unsigned short)(u >> 16));
                    }
                } else if (o < 64) {
                    float bias = bk[o - 32];
                    #pragma unroll
                    for (int f = 0; f < 4; f++) {
                        int n = nbase + f * 8 + cb;
                        unsigned u = bf2(acc[t][f][h * 2]     + bias,
                                         acc[t][f][h * 2 + 1] + bias);
                        sts16(XT + 10240 + n * 80 + (o - 32) * 2,
                              (unsigned short)(u & 0xffff));
                        sts16(XT + 10240 + (n + 1) * 80 + (o - 32) * 2,
                              (unsigned short)(u >> 16));
                    }
                } else {
                    float bias = bv[o - 64];
                    #pragma unroll
                    for (int f = 0; f < 4; f++) {
                        int n = nbase + f * 8 + cb;
                        unsigned u = bf2(acc[t][f][h * 2] + bias,
                                         acc[t][f][h * 2 + 1] + bias);
                        *(unsigned*)(g_v + ((size_t)(b * CDIM + o - 64)) * NPIX
                                     + n0 + n) = u;
                    }
                }
            }
        }
    }
    __syncthreads();
    // flat 16B copy of staged q/k tiles to gmem
    {
        __nv_bfloat16* gq = g_q + (size_t)(b * NPIX + n0) * 40;
        __nv_bfloat16* gk = g_k + (size_t)(b * NPIX + n0) * 40;
        for (int i = tid; i < 640; i += 512) {
            *(uint4*)(gq + i * 8) = *(uint4*)(smem + i * 16);
            *(uint4*)(gk + i * 8) = *(uint4*)(smem + 10240 + i * 16);
        }
    }
}

// ---------------------------------------------------------------------------
// flash attention, warp split: 2 q-groups (32q) x 4 key-slices/d-blocks
// grid (64, 4), 256 threads, occ 2
// smem: Q [64][80B] @0 (5120), K [128][80B] @5120 (10240),
//       P [64][272B] @15360 (17408), V [256][272B] @32768 (69632; Os overlay),
//       L [4][64] f32 @102400 (1024)
// ---------------------------------------------------------------------------
#define SQ_OFF 0
#define SK_OFF 5120
#define SP_OFF 15360
#define SV_OFF 32768
#define SL_OFF 102400
#define DSMEM  103424

__global__ __launch_bounds__(256, 2) void flash_mma(
    const float* __restrict__ x,
    const float* __restrict__ gamma,
    float* __restrict__ out)
{
    extern __shared__ char smem[];
    const unsigned sb = smem_u32(smem);

    const int tid  = threadIdx.x;
    const int lane = tid & 31;
    const int warp = tid >> 5;
    const int b    = blockIdx.y;
    const int n0   = blockIdx.x * CTA_Q;
    const int qg   = warp & 1;      // q-group (32 q)
    const int ksl  = warp >> 1;     // S: key slice (32 k); PV: d block (64 d)
    const int q0   = qg * 32;
    const int d0   = ksl * 64;

    // ---- stage Q tile (flat cp.async, already bf16 [n][40]) ----
    {
        const __nv_bfloat16* qb = g_q + (size_t)(b * NPIX + n0) * 40;
        for (int i = tid; i < 320; i += 256) CP16(sb + SQ_OFF + i * 16, qb + i * 8);
        CP_COMMIT(); CP_WAIT0();
    }
    __syncthreads();

    unsigned qa[2][2][4];
    #pragma unroll
    for (int mt = 0; mt < 2; mt++) {
        int rowa = q0 + mt * 16 + (lane & 7) + ((lane & 8) ? 8 : 0);
        #pragma unroll
        for (int cs = 0; cs < 2; cs++)
            ldmx4(qa[mt][cs], sb + SQ_OFF + rowa * 80 + cs * 32 +
                              ((lane & 16) ? 16 : 0));
    }

    float oacc[2][8][4];
    #pragma unroll
    for (int m = 0; m < 2; m++)
        #pragma unroll
        for (int i = 0; i < 8; i++)
            #pragma unroll
            for (int j = 0; j < 4; j++) oacc[m][i][j] = 0.f;
    float lr[4] = {0.f, 0.f, 0.f, 0.f};

    const int r  = lane >> 2;
    const int cb = (lane & 3) * 2;

    for (int kt = 0; kt < NPIX / KT; kt++) {
        __syncthreads();   // prev PV done: K/V/P smem free

        // ---- K tile flat cp.async (group 1) ----
        {
            const __nv_bfloat16* kb = g_k + (size_t)(b * NPIX + kt * KT) * 40;
            for (int i = tid; i < 640; i += 256) CP16(sb + SK_OFF + i * 16, kb + i * 8);
            CP_COMMIT();
        }
        // ---- V tile cp.async (group 2) ----
        {
            const __nv_bfloat16* vb = g_v + (size_t)b * CDIM * NPIX + kt * KT;
            #pragma unroll
            for (int it = 0; it < 16; it++) {
                int idx = it * 256 + tid;
                int d = idx >> 4, c = idx & 15;
                CP16(sb + SV_OFF + d * 272 + c * 16, vb + (size_t)d * NPIX + c * 8);
            }
            CP_COMMIT();
        }
        CP_WAIT1();        // K ready; V still in flight
        __syncthreads();

        // ---- S = Q.K^T over this warp's 32-key slice, exp, P -> smem ----
        #pragma unroll
        for (int kk = 0; kk < 2; kk++) {
            const int kb0 = ksl * 32 + kk * 16;
            unsigned kfr[2][4];
            {
                int nrow = kb0 + (lane & 7) + ((lane & 16) ? 8 : 0);
                #pragma unroll
                for (int cs = 0; cs < 2; cs++)
                    ldmx4(kfr[cs], sb + SK_OFF + nrow * 80 + cs * 32 +
                                   ((lane & 8) ? 16 : 0));
            }
            #pragma unroll
            for (int mt = 0; mt < 2; mt++) {
                float s0[4] = {0, 0, 0, 0}, s1[4] = {0, 0, 0, 0};
                mma16816(s0, qa[mt][0], kfr[0][0], kfr[0][1]);
                mma16816(s0, qa[mt][1], kfr[1][0], kfr[1][1]);
                mma16816(s1, qa[mt][0], kfr[0][2], kfr[0][3]);
                mma16816(s1, qa[mt][1], kfr[1][2], kfr[1][3]);

                const int ra = q0 + mt * 16 + r;
                #pragma unroll
                for (int nb = 0; nb < 2; nb++) {
                    float* s = nb ? s1 : s0;
                    float p0 = fexp2(s[0] * LOG2E);
                    float p1 = fexp2(s[1] * LOG2E);
                    float p2 = fexp2(s[2] * LOG2E);
                    float p3 = fexp2(s[3] * LOG2E);
                    lr[mt * 2 + 0] += p0 + p1;
                    lr[mt * 2 + 1] += p2 + p3;
                    int col = kb0 + nb * 8 + cb;
                    sts32(sb + SP_OFF + ra * 272 + col * 2,       bf2(p0, p1));
                    sts32(sb + SP_OFF + (ra + 8) * 272 + col * 2, bf2(p2, p3));
                }
            }
        }
        CP_WAIT0();        // V ready
        __syncthreads();   // P complete + V visible

        // ---- O += P.V^T : 32q x 64d per warp over 128k ----
        #pragma unroll
        for (int ks = 0; ks < 8; ks++) {
            unsigned pa[2][4];
            #pragma unroll
            for (int mt = 0; mt < 2; mt++) {
                int rowa = q0 + mt * 16 + (lane & 7) + ((lane & 8) ? 8 : 0);
                ldmx4(pa[mt], sb + SP_OFF + rowa * 272 + ks * 32 +
                              ((lane & 16) ? 16 : 0));
            }
            #pragma unroll
            for (int dg = 0; dg < 4; dg++) {
                unsigned vf[4];
                int drow = d0 + dg * 16 + (lane & 7) + ((lane & 16) ? 8 : 0);
                ldmx4(vf, sb + SV_OFF + drow * 272 + ks * 32 +
                          ((lane & 8) ? 16 : 0));
                #pragma unroll
                for (int mt = 0; mt < 2; mt++) {
                    mma16816(oacc[mt][dg * 2 + 0], pa[mt], vf[0], vf[1]);
                    mma16816(oacc[mt][dg * 2 + 1], pa[mt], vf[2], vf[3]);
                }
            }
        }
    }

    // ---- row-sum partials -> L[ksl][q] ----
    #pragma unroll
    for (int i = 0; i < 4; i++) {
        lr[i] += __shfl_xor_sync(0xffffffffu, lr[i], 1);
        lr[i] += __shfl_xor_sync(0xffffffffu, lr[i], 2);
    }
    if ((lane & 3) == 0) {
        float* Ls = (float*)(smem + SL_OFF) + ksl * 64;
        #pragma unroll
        for (int mt = 0; mt < 2; mt++) {
            Ls[q0 + mt * 16 + r]     = lr[mt * 2 + 0];
            Ls[q0 + mt * 16 + 8 + r] = lr[mt * 2 + 1];
        }
    }
    __syncthreads();       // V reads done; safe to overlay Os

    // ---- O frags -> smem overlay [64][260] f32 ----
    {
        float* Os = (float*)(smem + SV_OFF);
        #pragma unroll
        for (int mt = 0; mt < 2; mt++) {
            const int row = q0 + mt * 16 + r;
            #pragma unroll
            for (int dg = 0; dg < 4; dg++)
                #pragma unroll
                for (int nb = 0; nb < 2; nb++) {
                    int col = d0 + dg * 16 + nb * 8 + cb;
                    float* a = oacc[mt][dg * 2 + nb];
                    Os[row * 260 + col]           = a[0];
                    Os[row * 260 + col + 1]       = a[1];
                    Os[(row + 8) * 260 + col]     = a[2];
                    Os[(row + 8) * 260 + col + 1] = a[3];
                }
        }
    }
    __syncthreads();

    // ---- final: out[b][d][n0+q] = gamma/l * O[q][d] + x ----
    {
        const float g = gamma[0];
        const int q = tid & 63;
        const int dgr = tid >> 6;
        const float* Ls = (const float*)(smem + SL_OFF);
        const float linv = g / (Ls[q] + Ls[64 + q] + Ls[128 + q] + Ls[192 + q]);
        const float* Os = (const float*)(smem + SV_OFF);
        const float* xb = x + (size_t)b * CDIM * NPIX + n0 + q;
        float* ob = out + (size_t)b * CDIM * NPIX + n0 + q;
        #pragma unroll 8
        for (int i = 0; i < 64; i++) {
            int d = dgr * 64 + i;
            size_t go = (size_t)d * NPIX;
            ob[go] = Os[q * 260 + d] * linv + xb[go];
        }
    }
}

// ---------------------------------------------------------------------------
extern "C" void kernel_launch(void* const* d_in, const int* in_sizes, int n_in,
                              void* d_out, int out_size)
{
    const float* x     = (const float*)d_in[0];
    const float* wq    = (const float*)d_in[1];
    const float* bq    = (const float*)d_in[2];
    const float* wk    = (const float*)d_in[3];
    const float* bk    = (const float*)d_in[4];
    const float* wv    = (const float*)d_in[5];
    const float* bv    = (const float*)d_in[6];
    const float* gamma = (const float*)d_in[7];
    float* out = (float*)d_out;

    cudaFuncSetAttribute(qkv_proj, cudaFuncAttributeMaxDynamicSharedMemorySize,
                         PROJ_SMEM);
    qkv_proj<<<dim3(NPIX / 128, BATCH), 512, PROJ_SMEM>>>(x, wq, bq, wk, bk, wv, bv);

    cudaFuncSetAttribute(flash_mma, cudaFuncAttributeMaxDynamicSharedMemorySize,
                         DSMEM);
    flash_mma<<<dim3(NPIX / CTA_Q, BATCH), 256, DSMEM>>>(x, gamma, out);
}